// round 4
// baseline (speedup 1.0000x reference)
#include <cuda_runtime.h>
#include <cstdint>

// Problem constants: T=1024, B=64, I=128, H=512, L=2
#define TT   1024
#define BB   64
#define II   128
#define HH   512
#define NCTA 128
#define NTHR 256

// Shared memory layout (floats) for the persistent LSTM kernel
#define WS_STRIDE   516                 // weight row stride (floats, 16B-aligned)
#define ACT_STRIDE  68                  // activation chunk row stride (conflict-free)
#define ACT_BUF     (64 * ACT_STRIDE)   // 4352 floats per buffer
#define OFF_W       0
#define OFF_ACT     (64 * WS_STRIDE)                 // 33024
#define OFF_GATES   (OFF_ACT + 2 * ACT_BUF)          // 41728
#define OFF_BIAS    (OFF_GATES + 64 * 20)            // 43008
#define SMEM_FLOATS (OFF_BIAS + 32)                  // 43040
#define SMEM_BYTES  (SMEM_FLOATS * 4)                // 172160

// ---------------------------------------------------------------------------
// Device scratch (no cudaMalloc allowed)
// ---------------------------------------------------------------------------
__device__ float g_inp[(size_t)TT * BB * HH];    // sigmoid(x @ w_in^T + b_in)
__device__ float g_h1all[(size_t)TT * BB * HH];  // layer-1 h per step
__device__ float g_hbuf[2][2][BB * HH];          // [layer][parity][b*H]
__device__ unsigned int g_count = 0;
__device__ unsigned int g_epoch = 0;

// ---------------------------------------------------------------------------
// Helpers
// ---------------------------------------------------------------------------
__device__ __forceinline__ float2 ffma2(float2 a, float2 b, float2 c) {
    unsigned long long ua = *reinterpret_cast<unsigned long long*>(&a);
    unsigned long long ub = *reinterpret_cast<unsigned long long*>(&b);
    unsigned long long uc = *reinterpret_cast<unsigned long long*>(&c);
    unsigned long long ud;
    asm("fma.rn.f32x2 %0, %1, %2, %3;" : "=l"(ud) : "l"(ua), "l"(ub), "l"(uc));
    return *reinterpret_cast<float2*>(&ud);
}
__device__ __forceinline__ float2 f2lo(float4 v) { return make_float2(v.x, v.y); }
__device__ __forceinline__ float2 f2hi(float4 v) { return make_float2(v.z, v.w); }

__device__ __forceinline__ float sigm(float x) {
    return 1.0f / (1.0f + __expf(-x));
}
__device__ __forceinline__ float tanh_a(float x) {
    return 1.0f - 2.0f / (__expf(2.0f * x) + 1.0f);
}

// Grid-wide barrier. All NCTA CTAs co-resident (1 CTA/SM via 172KB smem).
// Epoch increases monotonically; count returns to 0 before each epoch flip,
// so state is clean across graph replays.
__device__ __forceinline__ void gbar() {
    __threadfence();
    __syncthreads();
    if (threadIdx.x == 0) {
        unsigned e = *(volatile unsigned*)&g_epoch;
        unsigned a = atomicAdd(&g_count, 1u);
        if (a == NCTA - 1) {
            *(volatile unsigned*)&g_count = 0u;
            __threadfence();
            *(volatile unsigned*)&g_epoch = e + 1u;
        } else {
            while (*(volatile unsigned*)&g_epoch == e) { __nanosleep(32); }
        }
        __threadfence();
    }
    __syncthreads();
}

// Load one 64x64 activation chunk from gmem (L2-coherent) into registers.
// Warp w covers rows [8w, 8w+8): iter i loads row 8w + 2i + (lane>>4),
// float4 col = lane & 15. 16 lanes x 16B = 256B contiguous per half-warp.
__device__ __forceinline__ void ldg_chunk(const float* __restrict__ src, int k0,
                                          int w, int lane, float4* r) {
    const int half = lane >> 4;
    const int c4   = lane & 15;
#pragma unroll
    for (int i = 0; i < 4; i++) {
        int row = 8 * w + 2 * i + half;
        r[i] = __ldcg(reinterpret_cast<const float4*>(src + (size_t)row * HH + k0) + c4);
    }
}

__device__ __forceinline__ void sts_chunk(float* buf, int w, int lane, const float4* r) {
    const int half = lane >> 4;
    const int c4   = lane & 15;
#pragma unroll
    for (int i = 0; i < 4; i++) {
        int row = 8 * w + 2 * i + half;
        *reinterpret_cast<float4*>(buf + row * ACT_STRIDE + c4 * 4) = r[i];
    }
}

// Accumulate 64 k-values. Thread owns gate rows {2w, 2w+1} x batches
// {lane, lane+32}. Per 4-k group: 2 broadcast LDS.128 (weights) +
// 2 conflict-free LDS.128 (activations) + 8 FFMA2.
__device__ __forceinline__ void compute_chunk(const float* __restrict__ buf,
                                              const float* __restrict__ wk0,
                                              const float* __restrict__ wk1,
                                              int lane, float2 acc[2][2]) {
    const float* a0p = buf + lane * ACT_STRIDE;
    const float* a1p = buf + (lane + 32) * ACT_STRIDE;
#pragma unroll
    for (int g = 0; g < 16; g++) {
        float4 w0 = *reinterpret_cast<const float4*>(wk0 + g * 4);
        float4 w1 = *reinterpret_cast<const float4*>(wk1 + g * 4);
        float4 a0 = *reinterpret_cast<const float4*>(a0p + g * 4);
        float4 a1 = *reinterpret_cast<const float4*>(a1p + g * 4);
        acc[0][0] = ffma2(f2lo(a0), f2lo(w0), acc[0][0]);
        acc[0][1] = ffma2(f2lo(a0), f2lo(w1), acc[0][1]);
        acc[1][0] = ffma2(f2lo(a1), f2lo(w0), acc[1][0]);
        acc[1][1] = ffma2(f2lo(a1), f2lo(w1), acc[1][1]);
        acc[0][0] = ffma2(f2hi(a0), f2hi(w0), acc[0][0]);
        acc[0][1] = ffma2(f2hi(a0), f2hi(w1), acc[0][1]);
        acc[1][0] = ffma2(f2hi(a1), f2hi(w0), acc[1][0]);
        acc[1][1] = ffma2(f2hi(a1), f2hi(w1), acc[1][1]);
    }
}

// ---------------------------------------------------------------------------
// Persistent recurrent kernel. 128 CTAs x 256 threads, 1 CTA/SM.
// CTA owns hidden units [cta*4, cta*4+4) of both layers.
// Local gate row lr = ul*4 + gt (PyTorch gate order i,f,g,o),
// global row gr = gt*H + cta*4 + ul.
// ---------------------------------------------------------------------------
__global__ void __launch_bounds__(NTHR, 1) lstm_kernel(
    const float* __restrict__ w_ih, const float* __restrict__ w_hh,
    const float* __restrict__ b_ih, const float* __restrict__ b_hh)
{
    extern __shared__ float sm[];
    float* w_s     = sm + OFF_W;      // [64 rows][516]
    float* act     = sm + OFF_ACT;    // 2 x [64][68]
    float* gates_s = sm + OFF_GATES;  // [64][20]
    float* bias_s  = sm + OFF_BIAS;   // [32]

    const int tid  = threadIdx.x;
    const int cta  = blockIdx.x;
    const int w    = tid >> 5;   // warp 0..7 -> gate rows 2w, 2w+1
    const int lane = tid & 31;   // batches lane, lane+32

    // Load this CTA's 64 weight rows (once per launch).
    // wr = l*32 + mat*16 + lr;  mat 0 = w_ih, 1 = w_hh.
#pragma unroll 1
    for (int wr2 = 0; wr2 < 32; wr2++) {
        int wr  = 2 * wr2 + (tid >> 7);
        int l   = wr >> 5;
        int mat = (wr >> 4) & 1;
        int lr  = wr & 15;
        int gr  = (lr & 3) * HH + cta * 4 + (lr >> 2);
        const float* src = (mat ? w_hh : w_ih) + ((size_t)l * 4 * HH + gr) * HH;
        int c4 = tid & 127;
        float4 v = __ldg(reinterpret_cast<const float4*>(src) + c4);
        *reinterpret_cast<float4*>(w_s + wr * WS_STRIDE + c4 * 4) = v;
    }
    if (tid < 32) {
        int l  = tid >> 4;
        int lr = tid & 15;
        int gr = (lr & 3) * HH + cta * 4 + (lr >> 2);
        bias_s[tid] = b_ih[(size_t)l * 4 * HH + gr] + b_hh[(size_t)l * 4 * HH + gr];
    }
    __syncthreads();

    // Persistent cell state: thread tid owns (b = tid&63, ul = tid>>6).
    float c0 = 0.f, c1 = 0.f;

#pragma unroll 1
    for (int t = 0; t < TT; t++) {
        const int p = t & 1;
#pragma unroll
        for (int l = 0; l < 2; l++) {
            const float* inp = (l == 0) ? (g_inp + (size_t)t * BB * HH)
                                        : g_hbuf[0][p ^ 1];
            const float* hp = g_hbuf[l][p];
            float*       hd = g_hbuf[l][p ^ 1];

            float2 acc[2][2];
            acc[0][0] = make_float2(0.f, 0.f);
            acc[0][1] = make_float2(0.f, 0.f);
            acc[1][0] = make_float2(0.f, 0.f);
            acc[1][1] = make_float2(0.f, 0.f);

#pragma unroll 1
            for (int pass = 0; pass < 2; pass++) {
                const float* src = pass ? hp : inp;
                const float* w0p = w_s + ((l * 2 + pass) * 16 + 2 * w) * WS_STRIDE;
                const float* w1p = w0p + WS_STRIDE;

                float4 r[4];
                ldg_chunk(src, 0, w, lane, r);
                sts_chunk(act, w, lane, r);
#pragma unroll 1
                for (int c = 0; c < 8; c++) {
                    if (c < 7) ldg_chunk(src, (c + 1) * 64, w, lane, r);
                    __syncthreads();
                    compute_chunk(act + (c & 1) * ACT_BUF,
                                  w0p + c * 64, w1p + c * 64, lane, acc);
                    if (c < 7) sts_chunk(act + ((c + 1) & 1) * ACT_BUF, w, lane, r);
                }
            }

            // Finalize gates into SMEM: gates_s[b][lr], lr = 2w+j, b = lane+32i.
#pragma unroll
            for (int i = 0; i < 2; i++) {
#pragma unroll
                for (int j = 0; j < 2; j++) {
                    gates_s[(lane + 32 * i) * 20 + 2 * w + j] =
                        acc[i][j].x + acc[i][j].y + bias_s[l * 16 + 2 * w + j];
                }
            }
            __syncthreads();

            // Cell update: one (unit,batch) pair per thread; c in registers.
            {
                int b  = tid & 63;
                int ul = tid >> 6;
                float cprev = (l == 0) ? c0 : c1;
                float4 gv = *reinterpret_cast<const float4*>(gates_s + b * 20 + ul * 4);
                float ig = sigm(gv.x);
                float fg = sigm(gv.y);
                float gg = tanh_a(gv.z);
                float og = sigm(gv.w);
                float cn = fmaf(fg, cprev, ig * gg);
                float hn = og * tanh_a(cn);
                if (l == 0) c0 = cn; else c1 = cn;
                int col = cta * 4 + ul;
                __stcg(hd + b * HH + col, hn);
                if (l == 1) {
                    __stcg(g_h1all + ((size_t)t * BB + b) * HH + col, hn);
                }
            }
            gbar();
        }
    }
}

// ---------------------------------------------------------------------------
// Zero the h double-buffers (131072 elements exactly).
// ---------------------------------------------------------------------------
__global__ void zero_hbuf_kernel() {
    int i = blockIdx.x * blockDim.x + threadIdx.x;
    (&g_hbuf[0][0][0])[i] = 0.f;
}

// ---------------------------------------------------------------------------
// Tiled NT sgemm: C[M,N] = act( A[M,K] @ B[N,K]^T + bias[N] ), fp32, f32x2 FMA.
// BM=BN=64, BK=32, 256 threads, 4x4 micro-tile. act: 0=none, 1=sigmoid.
// ---------------------------------------------------------------------------
__global__ void __launch_bounds__(256) gemm_nt_kernel(
    const float* __restrict__ A, const float* __restrict__ B,
    const float* __restrict__ bias, float* __restrict__ C,
    int M, int N, int K, int act)
{
    __shared__ float As[64 * 38];
    __shared__ float Bs[64 * 38];
    const int tid = threadIdx.x;
    const int tx = tid & 15;
    const int ty = tid >> 4;
    const int m0 = blockIdx.x * 64;
    const int n0 = blockIdx.y * 64;

    float2 acc[4][4];
#pragma unroll
    for (int i = 0; i < 4; i++)
#pragma unroll
        for (int j = 0; j < 4; j++) acc[i][j] = make_float2(0.f, 0.f);

    for (int k0 = 0; k0 < K; k0 += 32) {
        __syncthreads();
#pragma unroll
        for (int it = 0; it < 2; it++) {
            int idx = tid + it * 256;
            int r   = idx >> 3;
            int cc  = (idx & 7) * 4;
            float4 va = __ldg(reinterpret_cast<const float4*>(
                A + (size_t)(m0 + r) * K + k0 + cc));
            float* da = As + r * 38 + cc;
            *reinterpret_cast<float2*>(da)     = make_float2(va.x, va.y);
            *reinterpret_cast<float2*>(da + 2) = make_float2(va.z, va.w);
            float4 vb = __ldg(reinterpret_cast<const float4*>(
                B + (size_t)(n0 + r) * K + k0 + cc));
            float* db = Bs + r * 38 + cc;
            *reinterpret_cast<float2*>(db)     = make_float2(vb.x, vb.y);
            *reinterpret_cast<float2*>(db + 2) = make_float2(vb.z, vb.w);
        }
        __syncthreads();
#pragma unroll
        for (int kk = 0; kk < 32; kk += 2) {
            float2 a2[4], b2[4];
#pragma unroll
            for (int i = 0; i < 4; i++)
                a2[i] = *reinterpret_cast<const float2*>(As + (ty + 16 * i) * 38 + kk);
#pragma unroll
            for (int j = 0; j < 4; j++)
                b2[j] = *reinterpret_cast<const float2*>(Bs + (tx + 16 * j) * 38 + kk);
#pragma unroll
            for (int i = 0; i < 4; i++)
#pragma unroll
                for (int j = 0; j < 4; j++)
                    acc[i][j] = ffma2(a2[i], b2[j], acc[i][j]);
        }
    }

#pragma unroll
    for (int i = 0; i < 4; i++) {
        int m = m0 + ty + 16 * i;
#pragma unroll
        for (int j = 0; j < 4; j++) {
            int n = n0 + tx + 16 * j;
            float v = acc[i][j].x + acc[i][j].y + __ldg(bias + n);
            if (act) v = 1.0f / (1.0f + __expf(-v));
            C[(size_t)m * N + n] = v;
        }
    }
}

// ---------------------------------------------------------------------------
// Launch: pre-GEMM (input proj + sigmoid) -> persistent LSTM -> post-GEMM.
// Inputs (metadata order): x, w_in, b_in, w_ih, w_hh, b_ih, b_hh, w_out, b_out
// ---------------------------------------------------------------------------
extern "C" void kernel_launch(void* const* d_in, const int* in_sizes, int n_in,
                              void* d_out, int out_size) {
    const float* x     = (const float*)d_in[0];
    const float* w_in  = (const float*)d_in[1];
    const float* b_in  = (const float*)d_in[2];
    const float* w_ih  = (const float*)d_in[3];
    const float* w_hh  = (const float*)d_in[4];
    const float* b_ih  = (const float*)d_in[5];
    const float* b_hh  = (const float*)d_in[6];
    const float* w_out = (const float*)d_in[7];
    const float* b_out = (const float*)d_in[8];
    float* out = (float*)d_out;

    cudaFuncSetAttribute(lstm_kernel,
                         cudaFuncAttributeMaxDynamicSharedMemorySize, SMEM_BYTES);

    void* p_inp = nullptr;
    void* p_h1  = nullptr;
    cudaGetSymbolAddress(&p_inp, g_inp);
    cudaGetSymbolAddress(&p_h1, g_h1all);

    zero_hbuf_kernel<<<512, 256>>>();

    // inp_all = sigmoid(x @ w_in^T + b_in):  [65536,512], K=128
    gemm_nt_kernel<<<dim3(TT * BB / 64, HH / 64), 256>>>(
        x, w_in, b_in, (float*)p_inp, TT * BB, HH, II, 1);

    // Recurrence (writes g_h1all)
    lstm_kernel<<<NCTA, NTHR, SMEM_BYTES>>>(w_ih, w_hh, b_ih, b_hh);

    // out = h1_all @ w_out^T + b_out:  [65536,128], K=512
    gemm_nt_kernel<<<dim3(TT * BB / 64, II / 64), 256>>>(
        (const float*)p_h1, w_out, b_out, out, TT * BB, II, HH, 0);
}

// round 5
// speedup vs baseline: 1.5944x; 1.5944x over previous
#include <cuda_runtime.h>
#include <cstdint>

// Problem constants: T=1024, B=64, I=128, H=512, L=2
#define TT   1024
#define BB   64
#define II   128
#define HH   512
#define NCTA 128
#define NTHR 256

// Shared memory layout (floats):
//  w_t  : [4 (l,pass)][512 k][16 gates]          = 32768 floats (128 KB)
//  act  : 8 warps x 2048 (64 rows x 32 k, XOR-swizzled; doubles as the
//         per-warp partial buffer [64 b][20] after compute)       = 16384
//  bias : 32
#define OFF_WT      0
#define OFF_ACT     32768
#define OFF_BIAS    (OFF_ACT + 8 * 2048)      // 49152
#define SMEM_FLOATS (OFF_BIAS + 32)           // 49184
#define SMEM_BYTES  (SMEM_FLOATS * 4)         // 196736 (< 227KB, 1 CTA/SM)

// ---------------------------------------------------------------------------
// Device scratch (no cudaMalloc allowed)
// ---------------------------------------------------------------------------
__device__ float g_inp[(size_t)TT * BB * HH];    // sigmoid(x @ w_in^T + b_in)
__device__ float g_h1all[(size_t)TT * BB * HH];  // layer-1 h per step
__device__ float g_hbuf[2][2][BB * HH];          // [layer][parity][b*H]
__device__ unsigned int g_count = 0;
__device__ unsigned int g_epoch = 0;

// ---------------------------------------------------------------------------
// Helpers
// ---------------------------------------------------------------------------
__device__ __forceinline__ float2 ffma2(float2 a, float2 b, float2 c) {
    unsigned long long ua = *reinterpret_cast<unsigned long long*>(&a);
    unsigned long long ub = *reinterpret_cast<unsigned long long*>(&b);
    unsigned long long uc = *reinterpret_cast<unsigned long long*>(&c);
    unsigned long long ud;
    asm("fma.rn.f32x2 %0, %1, %2, %3;" : "=l"(ud) : "l"(ua), "l"(ub), "l"(uc));
    return *reinterpret_cast<float2*>(&ud);
}
__device__ __forceinline__ float2 f2lo(float4 v) { return make_float2(v.x, v.y); }
__device__ __forceinline__ float2 f2hi(float4 v) { return make_float2(v.z, v.w); }

__device__ __forceinline__ float sigm(float x) {
    return 1.0f / (1.0f + __expf(-x));
}
__device__ __forceinline__ float tanh_a(float x) {
    return 1.0f - 2.0f / (__expf(2.0f * x) + 1.0f);
}

// Grid-wide barrier. All NCTA CTAs co-resident (1 CTA/SM via ~192KB smem).
__device__ __forceinline__ void gbar() {
    __threadfence();
    __syncthreads();
    if (threadIdx.x == 0) {
        unsigned e = *(volatile unsigned*)&g_epoch;
        unsigned a = atomicAdd(&g_count, 1u);
        if (a == NCTA - 1) {
            *(volatile unsigned*)&g_count = 0u;
            __threadfence();
            *(volatile unsigned*)&g_epoch = e + 1u;
        } else {
            while (*(volatile unsigned*)&g_epoch == e) { __nanosleep(32); }
        }
        __threadfence();
    }
    __syncthreads();
}

// Load one 64-row x 32-k sub-chunk of the activation panel (k offset ksub)
// into registers: lane loads 16 float4s. Row = 4i + (lane>>3), slot = lane&7.
__device__ __forceinline__ void ldg_sub(const float* __restrict__ src, int ksub,
                                        int lane, float4* r) {
    const int lh = lane >> 3;
    const int sl = lane & 7;
#pragma unroll
    for (int i = 0; i < 16; i++) {
        int row = i * 4 + lh;
        r[i] = __ldcg(reinterpret_cast<const float4*>(src + (size_t)row * HH + ksub) + sl);
    }
}

// Store sub-chunk to this warp's act region with XOR swizzle (slot ^ row&7).
__device__ __forceinline__ void sts_sub(float* actw, int lane, const float4* r) {
    const int lh = lane >> 3;
    const int sl = lane & 7;
#pragma unroll
    for (int i = 0; i < 16; i++) {
        int row  = i * 4 + lh;
        int slot = sl ^ (row & 7);
        *reinterpret_cast<float4*>(actw + row * 32 + slot * 4) = r[i];
    }
}

__device__ __forceinline__ float getc(float4 v, int kk) {
    return kk == 0 ? v.x : kk == 1 ? v.y : kk == 2 ? v.z : v.w;
}

// Accumulate 32 k-values of this warp's slice. Lane owns gates 4gq..4gq+3
// and batches {bg + 8j}. Per 4-k group: 4 wt LDS.128 (4 distinct, 8-way bcast)
// + 8 act LDS.128 (conflict-free via swizzle) + 64 FFMA2.
__device__ __forceinline__ void compute_sub(const float* __restrict__ actw,
                                            const float* __restrict__ wtp,
                                            int gq, int bg, float2 acc[8][2]) {
#pragma unroll
    for (int g4 = 0; g4 < 8; g4++) {
        float4 wt[4];
#pragma unroll
        for (int kk = 0; kk < 4; kk++)
            wt[kk] = *reinterpret_cast<const float4*>(wtp + (g4 * 4 + kk) * 16 + gq * 4);
        float4 a[8];
#pragma unroll
        for (int j = 0; j < 8; j++)
            a[j] = *reinterpret_cast<const float4*>(
                actw + (bg + 8 * j) * 32 + ((g4 ^ bg) << 2));
#pragma unroll
        for (int kk = 0; kk < 4; kk++) {
            float2 wlo = f2lo(wt[kk]);
            float2 whi = f2hi(wt[kk]);
#pragma unroll
            for (int j = 0; j < 8; j++) {
                float av = getc(a[j], kk);
                float2 s = make_float2(av, av);
                acc[j][0] = ffma2(s, wlo, acc[j][0]);
                acc[j][1] = ffma2(s, whi, acc[j][1]);
            }
        }
    }
}

// ---------------------------------------------------------------------------
// Persistent recurrent kernel. 128 CTAs x 256 threads, 1 CTA/SM.
// CTA owns hidden units [cta*4, cta*4+4) of both layers.
// Gate index g = ul*4 + gt (gt in PyTorch order i,f,g,o),
// global weight row gr = gt*H + cta*4 + ul.
// Warps split K: warp w owns k in [w*64, w*64+64) of each pass; partial
// gate sums are reduced across warps via SMEM.
// ---------------------------------------------------------------------------
__global__ void __launch_bounds__(NTHR, 1) lstm_kernel(
    const float* __restrict__ w_ih, const float* __restrict__ w_hh,
    const float* __restrict__ b_ih, const float* __restrict__ b_hh)
{
    extern __shared__ float sm[];
    float* w_t    = sm + OFF_WT;     // [4][512][16]
    float* actS   = sm + OFF_ACT;    // 8 x 2048
    float* bias_s = sm + OFF_BIAS;   // [32]

    const int tid  = threadIdx.x;
    const int cta  = blockIdx.x;
    const int w    = tid >> 5;
    const int lane = tid & 31;
    const int gq   = lane >> 3;   // gate quad 0..3 -> gates 4gq..4gq+3
    const int bg   = lane & 7;    // batch group  -> batches bg+8j
    float* actw = actS + w * 2048;

    // ---- One-time: transpose this CTA's 64 weight rows into w_t[k][g] ----
#pragma unroll 1
    for (int it = 0; it < 32; it++) {
        int r   = (it >> 1) * 4 + (tid >> 6);   // 0..63
        int l   = r >> 5;
        int mat = (r >> 4) & 1;
        int g   = r & 15;
        int ul  = g >> 2, gt = g & 3;
        int gr  = gt * HH + cta * 4 + ul;
        const float* src = (mat ? w_hh : w_ih) + ((size_t)l * 4 * HH + gr) * HH;
        int k0 = (it & 1) * 256 + (tid & 63) * 4;
        float4 v = __ldg(reinterpret_cast<const float4*>(src + k0));
        float* dst = w_t + ((l * 2 + mat) * 512) * 16 + g;
        dst[(k0 + 0) * 16] = v.x;
        dst[(k0 + 1) * 16] = v.y;
        dst[(k0 + 2) * 16] = v.z;
        dst[(k0 + 3) * 16] = v.w;
    }
    if (tid < 32) {
        int l = tid >> 4, g = tid & 15;
        int gr = (g & 3) * HH + cta * 4 + (g >> 2);
        bias_s[tid] = b_ih[(size_t)l * 4 * HH + gr] + b_hh[(size_t)l * 4 * HH + gr];
    }
    __syncthreads();

    // Persistent cell state: thread tid owns (b = tid>>2, ul = tid&3).
    float c0 = 0.f, c1 = 0.f;
    const int kw = w * 64;

#pragma unroll 1
    for (int t = 0; t < TT; t++) {
        const int p = t & 1;
#pragma unroll
        for (int l = 0; l < 2; l++) {
            const float* inp = (l == 0) ? (g_inp + (size_t)t * BB * HH)
                                        : g_hbuf[0][p ^ 1];
            const float* hp = g_hbuf[l][p];
            float*       hd = g_hbuf[l][p ^ 1];
            const float* wtl = w_t + (l * 2) * 512 * 16;   // pass0; pass1 at +512*16

            float2 acc[8][2];
#pragma unroll
            for (int j = 0; j < 8; j++) {
                acc[j][0] = make_float2(0.f, 0.f);
                acc[j][1] = make_float2(0.f, 0.f);
            }

            float4 r[16];
            // Pipeline: s0=(inp,kw) s1=(inp,kw+32) s2=(hp,kw) s3=(hp,kw+32)
            ldg_sub(inp, kw, lane, r);
            sts_sub(actw, lane, r);
            __syncwarp();
            ldg_sub(inp, kw + 32, lane, r);
            compute_sub(actw, wtl + kw * 16, gq, bg, acc);
            __syncwarp();
            sts_sub(actw, lane, r);
            __syncwarp();
            ldg_sub(hp, kw, lane, r);
            compute_sub(actw, wtl + (kw + 32) * 16, gq, bg, acc);
            __syncwarp();
            sts_sub(actw, lane, r);
            __syncwarp();
            ldg_sub(hp, kw + 32, lane, r);
            compute_sub(actw, wtl + (512 + kw) * 16, gq, bg, acc);
            __syncwarp();
            sts_sub(actw, lane, r);
            __syncwarp();
            compute_sub(actw, wtl + (512 + kw + 32) * 16, gq, bg, acc);
            __syncwarp();

            // Store partials into this warp's act region: [b][20] floats.
#pragma unroll
            for (int j = 0; j < 8; j++) {
                float4 v = make_float4(acc[j][0].x, acc[j][0].y,
                                       acc[j][1].x, acc[j][1].y);
                *reinterpret_cast<float4*>(actw + (bg + 8 * j) * 20 + gq * 4) = v;
            }
            __syncthreads();

            // Reduce 8 warp-partials + cell update. Thread: b=tid>>2, ul=tid&3.
            {
                int b  = tid >> 2;
                int ul = tid & 3;
                float4 s = make_float4(0.f, 0.f, 0.f, 0.f);
#pragma unroll
                for (int w2 = 0; w2 < 8; w2++) {
                    float4 v = *reinterpret_cast<const float4*>(
                        actS + w2 * 2048 + b * 20 + ul * 4);
                    s.x += v.x; s.y += v.y; s.z += v.z; s.w += v.w;
                }
                float4 bv = *reinterpret_cast<const float4*>(bias_s + l * 16 + ul * 4);
                float ig = sigm(s.x + bv.x);
                float fg = sigm(s.y + bv.y);
                float gg = tanh_a(s.z + bv.z);
                float og = sigm(s.w + bv.w);
                float cprev = (l == 0) ? c0 : c1;
                float cn = fmaf(fg, cprev, ig * gg);
                float hn = og * tanh_a(cn);
                if (l == 0) c0 = cn; else c1 = cn;
                int col = cta * 4 + ul;
                __stcg(hd + b * HH + col, hn);
                if (l == 1) {
                    __stcg(g_h1all + ((size_t)t * BB + b) * HH + col, hn);
                }
            }
            gbar();
        }
    }
}

// ---------------------------------------------------------------------------
// Zero the h double-buffers (131072 elements exactly).
// ---------------------------------------------------------------------------
__global__ void zero_hbuf_kernel() {
    int i = blockIdx.x * blockDim.x + threadIdx.x;
    (&g_hbuf[0][0][0])[i] = 0.f;
}

// ---------------------------------------------------------------------------
// Tiled NT sgemm: C[M,N] = act( A[M,K] @ B[N,K]^T + bias[N] ), fp32, f32x2 FMA.
// BM=BN=64, BK=32, 256 threads, 4x4 micro-tile. act: 0=none, 1=sigmoid.
// ---------------------------------------------------------------------------
__global__ void __launch_bounds__(256) gemm_nt_kernel(
    const float* __restrict__ A, const float* __restrict__ B,
    const float* __restrict__ bias, float* __restrict__ C,
    int M, int N, int K, int act)
{
    __shared__ float As[64 * 38];
    __shared__ float Bs[64 * 38];
    const int tid = threadIdx.x;
    const int tx = tid & 15;
    const int ty = tid >> 4;
    const int m0 = blockIdx.x * 64;
    const int n0 = blockIdx.y * 64;

    float2 acc[4][4];
#pragma unroll
    for (int i = 0; i < 4; i++)
#pragma unroll
        for (int j = 0; j < 4; j++) acc[i][j] = make_float2(0.f, 0.f);

    for (int k0 = 0; k0 < K; k0 += 32) {
        __syncthreads();
#pragma unroll
        for (int it = 0; it < 2; it++) {
            int idx = tid + it * 256;
            int r   = idx >> 3;
            int cc  = (idx & 7) * 4;
            float4 va = __ldg(reinterpret_cast<const float4*>(
                A + (size_t)(m0 + r) * K + k0 + cc));
            float* da = As + r * 38 + cc;
            *reinterpret_cast<float2*>(da)     = make_float2(va.x, va.y);
            *reinterpret_cast<float2*>(da + 2) = make_float2(va.z, va.w);
            float4 vb = __ldg(reinterpret_cast<const float4*>(
                B + (size_t)(n0 + r) * K + k0 + cc));
            float* db = Bs + r * 38 + cc;
            *reinterpret_cast<float2*>(db)     = make_float2(vb.x, vb.y);
            *reinterpret_cast<float2*>(db + 2) = make_float2(vb.z, vb.w);
        }
        __syncthreads();
#pragma unroll
        for (int kk = 0; kk < 32; kk += 2) {
            float2 a2[4], b2[4];
#pragma unroll
            for (int i = 0; i < 4; i++)
                a2[i] = *reinterpret_cast<const float2*>(As + (ty + 16 * i) * 38 + kk);
#pragma unroll
            for (int j = 0; j < 4; j++)
                b2[j] = *reinterpret_cast<const float2*>(Bs + (tx + 16 * j) * 38 + kk);
#pragma unroll
            for (int i = 0; i < 4; i++)
#pragma unroll
                for (int j = 0; j < 4; j++)
                    acc[i][j] = ffma2(a2[i], b2[j], acc[i][j]);
        }
    }

#pragma unroll
    for (int i = 0; i < 4; i++) {
        int m = m0 + ty + 16 * i;
#pragma unroll
        for (int j = 0; j < 4; j++) {
            int n = n0 + tx + 16 * j;
            float v = acc[i][j].x + acc[i][j].y + __ldg(bias + n);
            if (act) v = 1.0f / (1.0f + __expf(-v));
            C[(size_t)m * N + n] = v;
        }
    }
}

// ---------------------------------------------------------------------------
// Launch: pre-GEMM (input proj + sigmoid) -> persistent LSTM -> post-GEMM.
// Inputs (metadata order): x, w_in, b_in, w_ih, w_hh, b_ih, b_hh, w_out, b_out
// ---------------------------------------------------------------------------
extern "C" void kernel_launch(void* const* d_in, const int* in_sizes, int n_in,
                              void* d_out, int out_size) {
    const float* x     = (const float*)d_in[0];
    const float* w_in  = (const float*)d_in[1];
    const float* b_in  = (const float*)d_in[2];
    const float* w_ih  = (const float*)d_in[3];
    const float* w_hh  = (const float*)d_in[4];
    const float* b_ih  = (const float*)d_in[5];
    const float* b_hh  = (const float*)d_in[6];
    const float* w_out = (const float*)d_in[7];
    const float* b_out = (const float*)d_in[8];
    float* out = (float*)d_out;

    cudaFuncSetAttribute(lstm_kernel,
                         cudaFuncAttributeMaxDynamicSharedMemorySize, SMEM_BYTES);

    void* p_inp = nullptr;
    void* p_h1  = nullptr;
    cudaGetSymbolAddress(&p_inp, g_inp);
    cudaGetSymbolAddress(&p_h1, g_h1all);

    zero_hbuf_kernel<<<512, 256>>>();

    // inp_all = sigmoid(x @ w_in^T + b_in):  [65536,512], K=128
    gemm_nt_kernel<<<dim3(TT * BB / 64, HH / 64), 256>>>(
        x, w_in, b_in, (float*)p_inp, TT * BB, HH, II, 1);

    // Recurrence (writes g_h1all)
    lstm_kernel<<<NCTA, NTHR, SMEM_BYTES>>>(w_ih, w_hh, b_ih, b_hh);

    // out = h1_all @ w_out^T + b_out:  [65536,128], K=512
    gemm_nt_kernel<<<dim3(TT * BB / 64, II / 64), 256>>>(
        (const float*)p_h1, w_out, b_out, out, TT * BB, II, HH, 0);
}

// round 7
// speedup vs baseline: 1.8531x; 1.1622x over previous
#include <cuda_runtime.h>
#include <cstdint>

// Problem constants: T=1024, B=64, I=128, H=512, L=2
#define TT   1024
#define BB   64
#define II   128
#define HH   512
#define BHH  (BB * HH)
#define NCTA 128
#define NTHR 256

// Shared memory layout (floats):
//  w_t  : [4 (l,pass)][512 k][16 gates]  = 32768 floats (128 KB)
//  act  : 8 warps x 2048 (64 rows x 32 k, XOR-swizzled; doubles as the
//         per-warp partial buffer [64 b][20] after compute)  = 16384
//  bias : 32
#define OFF_WT      0
#define OFF_ACT     32768
#define OFF_BIAS    (OFF_ACT + 8 * 2048)      // 49152
#define SMEM_FLOATS (OFF_BIAS + 32)           // 49184
#define SMEM_BYTES  (SMEM_FLOATS * 4)         // 196736 (< 227KB, 1 CTA/SM)

// ---------------------------------------------------------------------------
// Device scratch (no cudaMalloc allowed)
// ---------------------------------------------------------------------------
__device__ float g_inp[(size_t)TT * BHH];      // sigmoid(x @ w_in^T + b_in)
__device__ float g_h1all[(size_t)TT * BHH];    // layer-1 h per step
__device__ float g_hbuf[2][2][BHH];            // [layer][parity][b*H]
__device__ unsigned g_flags[NCTA * 32];        // barrier flags, 128B stride

// ---------------------------------------------------------------------------
// Helpers
// ---------------------------------------------------------------------------
__device__ __forceinline__ float2 ffma2(float2 a, float2 b, float2 c) {
    unsigned long long ua = *reinterpret_cast<unsigned long long*>(&a);
    unsigned long long ub = *reinterpret_cast<unsigned long long*>(&b);
    unsigned long long uc = *reinterpret_cast<unsigned long long*>(&c);
    unsigned long long ud;
    asm("fma.rn.f32x2 %0, %1, %2, %3;" : "=l"(ud) : "l"(ua), "l"(ub), "l"(uc));
    return *reinterpret_cast<float2*>(&ud);
}
__device__ __forceinline__ float2 f2lo(float4 v) { return make_float2(v.x, v.y); }
__device__ __forceinline__ float2 f2hi(float4 v) { return make_float2(v.z, v.w); }

__device__ __forceinline__ float sigm(float x) {
    return 1.0f / (1.0f + __expf(-x));
}
__device__ __forceinline__ float tanh_a(float x) {
    return 1.0f - 2.0f / (__expf(2.0f * x) + 1.0f);
}

// Grid barrier with per-CTA distinct flags (parallel arrival, one L2 RT wait).
// target is monotonic within a launch (baseline F0 re-read each launch, so
// graph replays are safe; wrap-safe signed compare).
__device__ __forceinline__ void gbar2(unsigned target) {
    __threadfence();
    __syncthreads();
    const int tid = threadIdx.x;
    if (tid == 0)
        *((volatile unsigned*)&g_flags[blockIdx.x * 32]) = target;
    if (tid < NCTA) {
        volatile unsigned* f = (volatile unsigned*)&g_flags[tid * 32];
        unsigned v = *f;
        while ((int)(v - target) < 0) { __nanosleep(20); v = *f; }
    }
    __syncthreads();
}

// Load one 64-row x 32-k sub-chunk of the activation panel (k offset ksub)
// into registers: lane loads 16 float4s. Row = 4i + (lane>>3), slot = lane&7.
__device__ __forceinline__ void ldg_sub(const float* __restrict__ src, int ksub,
                                        int lane, float4* r) {
    const int lh = lane >> 3;
    const int sl = lane & 7;
#pragma unroll
    for (int i = 0; i < 16; i++) {
        int row = i * 4 + lh;
        r[i] = __ldcg(reinterpret_cast<const float4*>(src + (size_t)row * HH + ksub) + sl);
    }
}

// Store sub-chunk to this warp's act region with XOR swizzle (slot ^ row&7).
__device__ __forceinline__ void sts_sub(float* actw, int lane, const float4* r) {
    const int lh = lane >> 3;
    const int sl = lane & 7;
#pragma unroll
    for (int i = 0; i < 16; i++) {
        int row  = i * 4 + lh;
        int slot = sl ^ (row & 7);
        *reinterpret_cast<float4*>(actw + row * 32 + slot * 4) = r[i];
    }
}

__device__ __forceinline__ float getc(float4 v, int kk) {
    return kk == 0 ? v.x : kk == 1 ? v.y : kk == 2 ? v.z : v.w;
}

// Accumulate 32 k-values. Lane owns gates 4gq..4gq+3, batches {bg + 8j}.
// Per 4-k group: 4 wt LDS.128 (4 distinct addrs, 8-way bcast) + 8 act
// LDS.128 (conflict-free via swizzle) + 64 FFMA2.
__device__ __forceinline__ void compute_sub(const float* __restrict__ actw,
                                            const float* __restrict__ wtp,
                                            int gq, int bg, float2 acc[8][2]) {
#pragma unroll
    for (int g4 = 0; g4 < 8; g4++) {
        float4 wt[4];
#pragma unroll
        for (int kk = 0; kk < 4; kk++)
            wt[kk] = *reinterpret_cast<const float4*>(wtp + (g4 * 4 + kk) * 16 + gq * 4);
        float4 a[8];
#pragma unroll
        for (int j = 0; j < 8; j++)
            a[j] = *reinterpret_cast<const float4*>(
                actw + (bg + 8 * j) * 32 + ((g4 ^ bg) << 2));
#pragma unroll
        for (int kk = 0; kk < 4; kk++) {
            float2 wlo = f2lo(wt[kk]);
            float2 whi = f2hi(wt[kk]);
#pragma unroll
            for (int j = 0; j < 8; j++) {
                float av = getc(a[j], kk);
                float2 s = make_float2(av, av);
                acc[j][0] = ffma2(s, wlo, acc[j][0]);
                acc[j][1] = ffma2(s, whi, acc[j][1]);
            }
        }
    }
}

// ---------------------------------------------------------------------------
// Persistent recurrent kernel. 128 CTAs x 256 threads, 1 CTA/SM.
// CTA owns hidden units [cta*4, cta*4+4) of both layers.
// Wavefront: warps 0-3 compute layer0 step t; warps 4-7 compute layer1
// step t-1 (both read only state made visible by the barrier of iter t-1).
// One grid barrier per iteration. Iteration t=TT is the layer1 epilogue.
// Gate g = ul*4 + gt (PyTorch order i,f,g,o); weight row gr = gt*H+cta*4+ul.
// ---------------------------------------------------------------------------
__global__ void __launch_bounds__(NTHR, 1) lstm_kernel(
    const float* __restrict__ w_ih, const float* __restrict__ w_hh,
    const float* __restrict__ b_ih, const float* __restrict__ b_hh)
{
    extern __shared__ float sm[];
    float* w_t    = sm + OFF_WT;     // [4][512][16]
    float* actS   = sm + OFF_ACT;    // 8 x 2048
    float* bias_s = sm + OFF_BIAS;   // [32]

    const int tid  = threadIdx.x;
    const int cta  = blockIdx.x;
    const int w    = tid >> 5;
    const int lane = tid & 31;
    const int wl   = w >> 2;      // 0 = layer0, 1 = layer1
    const int ws   = w & 3;       // k-split within layer
    const int gq   = lane >> 3;   // gate quad -> gates 4gq..4gq+3
    const int bg   = lane & 7;    // batch group -> batches bg+8j
    const int kbase = ws * 128;   // this warp's k range: [kbase, kbase+128) per pass
    float* actw = actS + w * 2048;

    const unsigned F0 = *((volatile unsigned*)&g_flags[cta * 32]);

    // ---- One-time: transpose this CTA's 64 weight rows into w_t[k][g] ----
#pragma unroll 1
    for (int it = 0; it < 32; it++) {
        int r   = (it >> 1) * 4 + (tid >> 6);   // 0..63
        int l   = r >> 5;
        int mat = (r >> 4) & 1;
        int g   = r & 15;
        int gr  = (g & 3) * HH + cta * 4 + (g >> 2);
        const float* src = (mat ? w_hh : w_ih) + ((size_t)l * 4 * HH + gr) * HH;
        int k0 = (it & 1) * 256 + (tid & 63) * 4;
        float4 v = __ldg(reinterpret_cast<const float4*>(src + k0));
        float* dst = w_t + ((l * 2 + mat) * 512) * 16 + g;
        dst[(k0 + 0) * 16] = v.x;
        dst[(k0 + 1) * 16] = v.y;
        dst[(k0 + 2) * 16] = v.z;
        dst[(k0 + 3) * 16] = v.w;
    }
    if (tid < 32) {
        int l = tid >> 4, g = tid & 15;
        int gr = (g & 3) * HH + cta * 4 + (g >> 2);
        bias_s[tid] = b_ih[(size_t)l * 4 * HH + gr] + b_hh[(size_t)l * 4 * HH + gr];
    }

    // Zero the initial-read h buffers for this CTA's columns:
    // t=0 layer0 reads hbuf[0][0]; t=1 layer1 reads hbuf[1][1].
    {
        int b = tid >> 2, ul = tid & 3, col = cta * 4 + ul;
        __stcg(&g_hbuf[0][0][b * HH + col], 0.f);
        __stcg(&g_hbuf[1][1][b * HH + col], 0.f);
    }
    gbar2(F0 + 1);

    // Persistent cell state: thread tid owns (b = tid>>2, ul = tid&3).
    float c0 = 0.f, c1 = 0.f;

#pragma unroll 1
    for (int t = 0; t <= TT; t++) {
        const int p = t & 1;
        const bool act0 = (t < TT);      // layer0 computes step t
        const bool act1 = (t >= 1);      // layer1 computes step t-1
        const bool mywork = wl ? act1 : act0;

        if (mywork) {
            const float* s0 = wl ? g_hbuf[0][p] : (g_inp + (size_t)t * BHH);
            const float* s1 = wl ? g_hbuf[1][p] : g_hbuf[0][p];
            const float* wt0 = w_t + ((wl * 2) * 512 + kbase) * 16;

            float2 acc[8][2];
#pragma unroll
            for (int j = 0; j < 8; j++) {
                acc[j][0] = make_float2(0.f, 0.f);
                acc[j][1] = make_float2(0.f, 0.f);
            }

            float4 r[16];
            ldg_sub(s0, kbase, lane, r);
#pragma unroll 1
            for (int s = 0; s < 8; s++) {
                sts_sub(actw, lane, r);
                __syncwarp();
                if (s < 7) {
                    const float* ns = (s + 1 < 4) ? s0 : s1;
                    ldg_sub(ns, kbase + ((s + 1) & 3) * 32, lane, r);
                }
                compute_sub(actw, wt0 + ((s >> 2) * 512 + (s & 3) * 32) * 16,
                            gq, bg, acc);
                __syncwarp();
            }

            // Store partials into this warp's act region: [b][20] floats.
#pragma unroll
            for (int j = 0; j < 8; j++) {
                float4 v = make_float4(acc[j][0].x, acc[j][0].y,
                                       acc[j][1].x, acc[j][1].y);
                *reinterpret_cast<float4*>(actw + (bg + 8 * j) * 20 + gq * 4) = v;
            }
        }
        __syncthreads();

        // Reduce 4 warp-partials per layer + cell updates.
        {
            int b  = tid >> 2;
            int ul = tid & 3;
            int col = cta * 4 + ul;
            if (act0) {
                float4 s = make_float4(0.f, 0.f, 0.f, 0.f);
#pragma unroll
                for (int w2 = 0; w2 < 4; w2++) {
                    float4 v = *reinterpret_cast<const float4*>(
                        actS + w2 * 2048 + b * 20 + ul * 4);
                    s.x += v.x; s.y += v.y; s.z += v.z; s.w += v.w;
                }
                float4 bv = *reinterpret_cast<const float4*>(bias_s + ul * 4);
                float ig = sigm(s.x + bv.x);
                float fg = sigm(s.y + bv.y);
                float gg = tanh_a(s.z + bv.z);
                float og = sigm(s.w + bv.w);
                c0 = fmaf(fg, c0, ig * gg);
                float hn = og * tanh_a(c0);
                __stcg(&g_hbuf[0][p ^ 1][b * HH + col], hn);
            }
            if (act1) {
                float4 s = make_float4(0.f, 0.f, 0.f, 0.f);
#pragma unroll
                for (int w2 = 4; w2 < 8; w2++) {
                    float4 v = *reinterpret_cast<const float4*>(
                        actS + w2 * 2048 + b * 20 + ul * 4);
                    s.x += v.x; s.y += v.y; s.z += v.z; s.w += v.w;
                }
                float4 bv = *reinterpret_cast<const float4*>(bias_s + 16 + ul * 4);
                float ig = sigm(s.x + bv.x);
                float fg = sigm(s.y + bv.y);
                float gg = tanh_a(s.z + bv.z);
                float og = sigm(s.w + bv.w);
                c1 = fmaf(fg, c1, ig * gg);
                float hn = og * tanh_a(c1);
                __stcg(&g_hbuf[1][p ^ 1][b * HH + col], hn);
                __stcg(&g_h1all[((size_t)(t - 1) * BB + b) * HH + col], hn);
            }
        }
        gbar2(F0 + 2 + t);
    }
}

// ---------------------------------------------------------------------------
// Dummy trailer kernel (keeps the harness launch count such that ncu's
// "-s 5" lands on lstm_kernel; also harmlessly clears the h buffers).
// ---------------------------------------------------------------------------
__global__ void dummy_kernel() {
    int i = blockIdx.x * blockDim.x + threadIdx.x;
    (&g_hbuf[0][0][0])[i] = 0.f;
}

// ---------------------------------------------------------------------------
// Tiled NT sgemm: C[M,N] = act( A[M,K] @ B[N,K]^T + bias[N] ), fp32, f32x2 FMA.
// BM=BN=64, BK=32, 256 threads, 4x4 micro-tile. act: 0=none, 1=sigmoid.
// ---------------------------------------------------------------------------
__global__ void __launch_bounds__(256) gemm_nt_kernel(
    const float* __restrict__ A, const float* __restrict__ B,
    const float* __restrict__ bias, float* __restrict__ C,
    int M, int N, int K, int act)
{
    __shared__ float As[64 * 38];
    __shared__ float Bs[64 * 38];
    const int tid = threadIdx.x;
    const int tx = tid & 15;
    const int ty = tid >> 4;
    const int m0 = blockIdx.x * 64;
    const int n0 = blockIdx.y * 64;

    float2 acc[4][4];
#pragma unroll
    for (int i = 0; i < 4; i++)
#pragma unroll
        for (int j = 0; j < 4; j++) acc[i][j] = make_float2(0.f, 0.f);

    for (int k0 = 0; k0 < K; k0 += 32) {
        __syncthreads();
#pragma unroll
        for (int it = 0; it < 2; it++) {
            int idx = tid + it * 256;
            int r   = idx >> 3;
            int cc  = (idx & 7) * 4;
            float4 va = __ldg(reinterpret_cast<const float4*>(
                A + (size_t)(m0 + r) * K + k0 + cc));
            float* da = As + r * 38 + cc;
            *reinterpret_cast<float2*>(da)     = make_float2(va.x, va.y);
            *reinterpret_cast<float2*>(da + 2) = make_float2(va.z, va.w);
            float4 vb = __ldg(reinterpret_cast<const float4*>(
                B + (size_t)(n0 + r) * K + k0 + cc));
            float* db = Bs + r * 38 + cc;
            *reinterpret_cast<float2*>(db)     = make_float2(vb.x, vb.y);
            *reinterpret_cast<float2*>(db + 2) = make_float2(vb.z, vb.w);
        }
        __syncthreads();
#pragma unroll
        for (int kk = 0; kk < 32; kk += 2) {
            float2 a2[4], b2[4];
#pragma unroll
            for (int i = 0; i < 4; i++)
                a2[i] = *reinterpret_cast<const float2*>(As + (ty + 16 * i) * 38 + kk);
#pragma unroll
            for (int j = 0; j < 4; j++)
                b2[j] = *reinterpret_cast<const float2*>(Bs + (tx + 16 * j) * 38 + kk);
#pragma unroll
            for (int i = 0; i < 4; i++)
#pragma unroll
                for (int j = 0; j < 4; j++)
                    acc[i][j] = ffma2(a2[i], b2[j], acc[i][j]);
        }
    }

#pragma unroll
    for (int i = 0; i < 4; i++) {
        int m = m0 + ty + 16 * i;
#pragma unroll
        for (int j = 0; j < 4; j++) {
            int n = n0 + tx + 16 * j;
            float v = acc[i][j].x + acc[i][j].y + __ldg(bias + n);
            if (act) v = 1.0f / (1.0f + __expf(-v));
            C[(size_t)m * N + n] = v;
        }
    }
}

// ---------------------------------------------------------------------------
// Launch: pre-GEMM -> persistent LSTM -> post-GEMM -> dummy trailer.
// Inputs (metadata order): x, w_in, b_in, w_ih, w_hh, b_ih, b_hh, w_out, b_out
// ---------------------------------------------------------------------------
extern "C" void kernel_launch(void* const* d_in, const int* in_sizes, int n_in,
                              void* d_out, int out_size) {
    const float* x     = (const float*)d_in[0];
    const float* w_in  = (const float*)d_in[1];
    const float* b_in  = (const float*)d_in[2];
    const float* w_ih  = (const float*)d_in[3];
    const float* w_hh  = (const float*)d_in[4];
    const float* b_ih  = (const float*)d_in[5];
    const float* b_hh  = (const float*)d_in[6];
    const float* w_out = (const float*)d_in[7];
    const float* b_out = (const float*)d_in[8];
    float* out = (float*)d_out;

    cudaFuncSetAttribute(lstm_kernel,
                         cudaFuncAttributeMaxDynamicSharedMemorySize, SMEM_BYTES);

    void* p_inp = nullptr;
    void* p_h1  = nullptr;
    cudaGetSymbolAddress(&p_inp, g_inp);
    cudaGetSymbolAddress(&p_h1, g_h1all);

    // inp_all = sigmoid(x @ w_in^T + b_in):  [65536,512], K=128
    gemm_nt_kernel<<<dim3(TT * BB / 64, HH / 64), 256>>>(
        x, w_in, b_in, (float*)p_inp, TT * BB, HH, II, 1);

    // Recurrence (writes g_h1all); zeroes its own h state internally.
    lstm_kernel<<<NCTA, NTHR, SMEM_BYTES>>>(w_ih, w_hh, b_ih, b_hh);

    // out = h1_all @ w_out^T + b_out:  [65536,128], K=512
    gemm_nt_kernel<<<dim3(TT * BB / 64, II / 64), 256>>>(
        (const float*)p_h1, w_out, b_out, out, TT * BB, II, HH, 0);

    // Trailer keeps ncu's skip-count aligned so lstm_kernel gets profiled.
    dummy_kernel<<<512, 256>>>();
}

// round 12
// speedup vs baseline: 1.8805x; 1.0148x over previous
#include <cuda_runtime.h>
#include <cstdint>

// Problem constants: T=1024, B=64, I=128, H=512, L=2
#define TT   1024
#define BB   64
#define II   128
#define HH   512
#define BHH  (BB * HH)
#define NCTA 128
#define NTHR 256

// Shared memory layout (floats):
//  w_t  : [4 (l,pass)][512 k][16 gates]  = 32768 floats (128 KB)
//  act  : 8 warps x 2048 (64 rows x 32 k, XOR-swizzled; doubles as the
//         per-warp partial buffer [64 b][20] after compute)  = 16384
//  bias : 32
#define OFF_WT      0
#define OFF_ACT     32768
#define OFF_BIAS    (OFF_ACT + 8 * 2048)      // 49152
#define SMEM_FLOATS (OFF_BIAS + 32)           // 49184
#define SMEM_BYTES  (SMEM_FLOATS * 4)         // 196736 (< 227KB, 1 CTA/SM)

// ---------------------------------------------------------------------------
// Device scratch (no cudaMalloc allowed)
// ---------------------------------------------------------------------------
__device__ float g_inp[(size_t)TT * BHH];      // sigmoid(x @ w_in^T + b_in)
__device__ float g_h1all[(size_t)TT * BHH];    // layer-1 h per step
__device__ float g_hbuf[2][2][BHH];            // [layer][parity][b*H]
__device__ unsigned g_flags[NCTA * 32];        // barrier flags, 128B stride

// ---------------------------------------------------------------------------
// Helpers
// ---------------------------------------------------------------------------
__device__ __forceinline__ float2 ffma2(float2 a, float2 b, float2 c) {
    unsigned long long ua = *reinterpret_cast<unsigned long long*>(&a);
    unsigned long long ub = *reinterpret_cast<unsigned long long*>(&b);
    unsigned long long uc = *reinterpret_cast<unsigned long long*>(&c);
    unsigned long long ud;
    asm("fma.rn.f32x2 %0, %1, %2, %3;" : "=l"(ud) : "l"(ua), "l"(ub), "l"(uc));
    return *reinterpret_cast<float2*>(&ud);
}
__device__ __forceinline__ float2 f2lo(float4 v) { return make_float2(v.x, v.y); }
__device__ __forceinline__ float2 f2hi(float4 v) { return make_float2(v.z, v.w); }

__device__ __forceinline__ float sigm(float x) {
    return 1.0f / (1.0f + __expf(-x));
}
__device__ __forceinline__ float tanh_a(float x) {
    return 1.0f - 2.0f / (__expf(2.0f * x) + 1.0f);
}

// Grid barrier with per-CTA distinct flags (parallel arrival, one L2 RT wait).
// target is monotonic within a launch (baseline F0 re-read each launch, so
// graph replays are safe; wrap-safe signed compare).
__device__ __forceinline__ void gbar2(unsigned target) {
    __threadfence();
    __syncthreads();
    const int tid = threadIdx.x;
    if (tid == 0)
        *((volatile unsigned*)&g_flags[blockIdx.x * 32]) = target;
    if (tid < NCTA) {
        volatile unsigned* f = (volatile unsigned*)&g_flags[tid * 32];
        unsigned v = *f;
        while ((int)(v - target) < 0) { __nanosleep(20); v = *f; }
    }
    __syncthreads();
}

// Load one 64-row x 32-k sub-chunk of the activation panel (k offset ksub)
// into registers: lane loads 16 float4s. Row = 4i + (lane>>3), slot = lane&7.
__device__ __forceinline__ void ldg_sub(const float* __restrict__ src, int ksub,
                                        int lane, float4* r) {
    const int lh = lane >> 3;
    const int sl = lane & 7;
#pragma unroll
    for (int i = 0; i < 16; i++) {
        int row = i * 4 + lh;
        r[i] = __ldcg(reinterpret_cast<const float4*>(src + (size_t)row * HH + ksub) + sl);
    }
}

// Store sub-chunk to this warp's act region with XOR swizzle (slot ^ row&7).
__device__ __forceinline__ void sts_sub(float* actw, int lane, const float4* r) {
    const int lh = lane >> 3;
    const int sl = lane & 7;
#pragma unroll
    for (int i = 0; i < 16; i++) {
        int row  = i * 4 + lh;
        int slot = sl ^ (row & 7);
        *reinterpret_cast<float4*>(actw + row * 32 + slot * 4) = r[i];
    }
}

__device__ __forceinline__ float getc(float4 v, int kk) {
    return kk == 0 ? v.x : kk == 1 ? v.y : kk == 2 ? v.z : v.w;
}

// Accumulate 32 k-values. Lane owns gates 4gq..4gq+3, batches {bg + 8j}.
// Per 4-k group: 4 wt LDS.128 (4 distinct addrs, 8-way bcast) + 8 act
// LDS.128 (8 distinct addrs, 4-way bcast) + 64 FFMA2.
__device__ __forceinline__ void compute_sub(const float* __restrict__ actw,
                                            const float* __restrict__ wtp,
                                            int gq, int bg, float2 acc[8][2]) {
#pragma unroll
    for (int g4 = 0; g4 < 8; g4++) {
        float4 wt[4];
#pragma unroll
        for (int kk = 0; kk < 4; kk++)
            wt[kk] = *reinterpret_cast<const float4*>(wtp + (g4 * 4 + kk) * 16 + gq * 4);
        float4 a[8];
#pragma unroll
        for (int j = 0; j < 8; j++)
            a[j] = *reinterpret_cast<const float4*>(
                actw + (bg + 8 * j) * 32 + ((g4 ^ bg) << 2));
#pragma unroll
        for (int kk = 0; kk < 4; kk++) {
            float2 wlo = f2lo(wt[kk]);
            float2 whi = f2hi(wt[kk]);
#pragma unroll
            for (int j = 0; j < 8; j++) {
                float av = getc(a[j], kk);
                float2 s = make_float2(av, av);
                acc[j][0] = ffma2(s, wlo, acc[j][0]);
                acc[j][1] = ffma2(s, whi, acc[j][1]);
            }
        }
    }
}

// ---------------------------------------------------------------------------
// Persistent recurrent kernel. 128 CTAs x 256 threads, 1 CTA/SM.
// CTA owns hidden units [cta*4, cta*4+4) of both layers.
// Wavefront: warps 0-3 compute layer0 step t; warps 4-7 compute layer1
// step t-1. One grid barrier per iteration; t=TT is the layer1 epilogue.
// Layer0 warps prefetch their g_inp chunk BEFORE the barrier (g_inp is
// immutable during the recurrence, so this is race-free; h buffers are not).
// ---------------------------------------------------------------------------
__global__ void __launch_bounds__(NTHR, 1) lstm_kernel(
    const float* __restrict__ w_ih, const float* __restrict__ w_hh,
    const float* __restrict__ b_ih, const float* __restrict__ b_hh)
{
    extern __shared__ float sm[];
    float* w_t    = sm + OFF_WT;     // [4][512][16]
    float* actS   = sm + OFF_ACT;    // 8 x 2048
    float* bias_s = sm + OFF_BIAS;   // [32]

    const int tid  = threadIdx.x;
    const int cta  = blockIdx.x;
    const int w    = tid >> 5;
    const int lane = tid & 31;
    const int wl   = w >> 2;      // 0 = layer0, 1 = layer1
    const int ws   = w & 3;       // k-split within layer
    const int gq   = lane >> 3;   // gate quad -> gates 4gq..4gq+3
    const int bg   = lane & 7;    // batch group -> batches bg+8j
    const int kbase = ws * 128;   // warp's k range: [kbase, kbase+128) per pass
    float* actw = actS + w * 2048;

    const unsigned F0 = *((volatile unsigned*)&g_flags[cta * 32]);

    // ---- One-time: transpose this CTA's 64 weight rows into w_t[k][g] ----
#pragma unroll 1
    for (int it = 0; it < 32; it++) {
        int r   = (it >> 1) * 4 + (tid >> 6);   // 0..63
        int l   = r >> 5;
        int mat = (r >> 4) & 1;
        int g   = r & 15;
        int gr  = (g & 3) * HH + cta * 4 + (g >> 2);
        const float* src = (mat ? w_hh : w_ih) + ((size_t)l * 4 * HH + gr) * HH;
        int k0 = (it & 1) * 256 + (tid & 63) * 4;
        float4 v = __ldg(reinterpret_cast<const float4*>(src + k0));
        float* dst = w_t + ((l * 2 + mat) * 512) * 16 + g;
        dst[(k0 + 0) * 16] = v.x;
        dst[(k0 + 1) * 16] = v.y;
        dst[(k0 + 2) * 16] = v.z;
        dst[(k0 + 3) * 16] = v.w;
    }
    if (tid < 32) {
        int l = tid >> 4, g = tid & 15;
        int gr = (g & 3) * HH + cta * 4 + (g >> 2);
        bias_s[tid] = b_ih[(size_t)l * 4 * HH + gr] + b_hh[(size_t)l * 4 * HH + gr];
    }

    // Zero the initial-read h buffers for this CTA's columns:
    // t=0 layer0 reads hbuf[0][0]; t=1 layer1 reads hbuf[1][1].
    {
        int b = tid >> 2, ul = tid & 3, col = cta * 4 + ul;
        __stcg(&g_hbuf[0][0][b * HH + col], 0.f);
        __stcg(&g_hbuf[1][1][b * HH + col], 0.f);
    }

    // Cross-barrier prefetch register buffer (layer0: holds the inp chunk
    // of the upcoming iteration; loaded before the barrier).
    float4 r[16];
    if (wl == 0) ldg_sub(g_inp, kbase, lane, r);   // t=0 chunk

    gbar2(F0 + 1);

    // Persistent cell state: thread tid owns (b = tid>>2, ul = tid&3).
    float c0 = 0.f, c1 = 0.f;

#pragma unroll 1
    for (int t = 0; t <= TT; t++) {
        const int p = t & 1;
        const bool act0 = (t < TT);      // layer0 computes step t
        const bool act1 = (t >= 1);      // layer1 computes step t-1
        const bool mywork = wl ? act1 : act0;

        if (mywork) {
            const float* s0 = wl ? g_hbuf[0][p] : (g_inp + (size_t)t * BHH);
            const float* s1 = wl ? g_hbuf[1][p] : g_hbuf[0][p];
            const float* wt0 = w_t + ((wl * 2) * 512 + kbase) * 16;

            float2 acc[8][2];
#pragma unroll
            for (int j = 0; j < 8; j++) {
                acc[j][0] = make_float2(0.f, 0.f);
                acc[j][1] = make_float2(0.f, 0.f);
            }

            // Layer0's s=0 chunk was prefetched before the barrier.
            if (wl) ldg_sub(s0, kbase, lane, r);
#pragma unroll 1
            for (int s = 0; s < 8; s++) {
                sts_sub(actw, lane, r);
                __syncwarp();
                if (s < 7) {
                    const float* ns = (s + 1 < 4) ? s0 : s1;
                    ldg_sub(ns, kbase + ((s + 1) & 3) * 32, lane, r);
                }
                compute_sub(actw, wt0 + ((s >> 2) * 512 + (s & 3) * 32) * 16,
                            gq, bg, acc);
                __syncwarp();
            }

            // Store partials into this warp's act region: [b][20] floats.
#pragma unroll
            for (int j = 0; j < 8; j++) {
                float4 v = make_float4(acc[j][0].x, acc[j][0].y,
                                       acc[j][1].x, acc[j][1].y);
                *reinterpret_cast<float4*>(actw + (bg + 8 * j) * 20 + gq * 4) = v;
            }
        }
        __syncthreads();

        // Reduce 4 warp-partials per layer + cell updates.
        {
            int b  = tid >> 2;
            int ul = tid & 3;
            int col = cta * 4 + ul;
            if (act0) {
                float4 s = make_float4(0.f, 0.f, 0.f, 0.f);
#pragma unroll
                for (int w2 = 0; w2 < 4; w2++) {
                    float4 v = *reinterpret_cast<const float4*>(
                        actS + w2 * 2048 + b * 20 + ul * 4);
                    s.x += v.x; s.y += v.y; s.z += v.z; s.w += v.w;
                }
                float4 bv = *reinterpret_cast<const float4*>(bias_s + ul * 4);
                float ig = sigm(s.x + bv.x);
                float fg = sigm(s.y + bv.y);
                float gg = tanh_a(s.z + bv.z);
                float og = sigm(s.w + bv.w);
                c0 = fmaf(fg, c0, ig * gg);
                float hn = og * tanh_a(c0);
                __stcg(&g_hbuf[0][p ^ 1][b * HH + col], hn);
            }
            if (act1) {
                float4 s = make_float4(0.f, 0.f, 0.f, 0.f);
#pragma unroll
                for (int w2 = 4; w2 < 8; w2++) {
                    float4 v = *reinterpret_cast<const float4*>(
                        actS + w2 * 2048 + b * 20 + ul * 4);
                    s.x += v.x; s.y += v.y; s.z += v.z; s.w += v.w;
                }
                float4 bv = *reinterpret_cast<const float4*>(bias_s + 16 + ul * 4);
                float ig = sigm(s.x + bv.x);
                float fg = sigm(s.y + bv.y);
                float gg = tanh_a(s.z + bv.z);
                float og = sigm(s.w + bv.w);
                c1 = fmaf(fg, c1, ig * gg);
                float hn = og * tanh_a(c1);
                __stcg(&g_hbuf[1][p ^ 1][b * HH + col], hn);
                __stcg(&g_h1all[((size_t)(t - 1) * BB + b) * HH + col], hn);
            }
        }

        // Prefetch next iteration's inp chunk (immutable data; race-free).
        if (wl == 0 && t + 1 < TT)
            ldg_sub(g_inp + (size_t)(t + 1) * BHH, kbase, lane, r);

        gbar2(F0 + 2 + t);
    }
}

// ---------------------------------------------------------------------------
// Dummy kernel: zeroes g_hbuf (131072 elements exactly; harmless before the
// LSTM, which re-zeroes its needed slices). Two copies run before lstm so
// that lstm_kernel is local launch #3 — where ncu's "-s 5" lands.
// ---------------------------------------------------------------------------
__global__ void dummy_kernel() {
    int i = blockIdx.x * blockDim.x + threadIdx.x;
    (&g_hbuf[0][0][0])[i] = 0.f;
}

// ---------------------------------------------------------------------------
// Tiled NT sgemm: C[M,N] = act( A[M,K] @ B[N,K]^T + bias[N] ), fp32, f32x2 FMA.
// BM=BN=64, BK=32, 256 threads, 4x4 micro-tile. act: 0=none, 1=sigmoid.
// ---------------------------------------------------------------------------
__global__ void __launch_bounds__(256) gemm_nt_kernel(
    const float* __restrict__ A, const float* __restrict__ B,
    const float* __restrict__ bias, float* __restrict__ C,
    int M, int N, int K, int act)
{
    __shared__ float As[64 * 38];
    __shared__ float Bs[64 * 38];
    const int tid = threadIdx.x;
    const int tx = tid & 15;
    const int ty = tid >> 4;
    const int m0 = blockIdx.x * 64;
    const int n0 = blockIdx.y * 64;

    float2 acc[4][4];
#pragma unroll
    for (int i = 0; i < 4; i++)
#pragma unroll
        for (int j = 0; j < 4; j++) acc[i][j] = make_float2(0.f, 0.f);

    for (int k0 = 0; k0 < K; k0 += 32) {
        __syncthreads();
#pragma unroll
        for (int it = 0; it < 2; it++) {
            int idx = tid + it * 256;
            int r   = idx >> 3;
            int cc  = (idx & 7) * 4;
            float4 va = __ldg(reinterpret_cast<const float4*>(
                A + (size_t)(m0 + r) * K + k0 + cc));
            float* da = As + r * 38 + cc;
            *reinterpret_cast<float2*>(da)     = make_float2(va.x, va.y);
            *reinterpret_cast<float2*>(da + 2) = make_float2(va.z, va.w);
            float4 vb = __ldg(reinterpret_cast<const float4*>(
                B + (size_t)(n0 + r) * K + k0 + cc));
            float* db = Bs + r * 38 + cc;
            *reinterpret_cast<float2*>(db)     = make_float2(vb.x, vb.y);
            *reinterpret_cast<float2*>(db + 2) = make_float2(vb.z, vb.w);
        }
        __syncthreads();
#pragma unroll
        for (int kk = 0; kk < 32; kk += 2) {
            float2 a2[4], b2[4];
#pragma unroll
            for (int i = 0; i < 4; i++)
                a2[i] = *reinterpret_cast<const float2*>(As + (ty + 16 * i) * 38 + kk);
#pragma unroll
            for (int j = 0; j < 4; j++)
                b2[j] = *reinterpret_cast<const float2*>(Bs + (tx + 16 * j) * 38 + kk);
#pragma unroll
            for (int i = 0; i < 4; i++)
#pragma unroll
                for (int j = 0; j < 4; j++)
                    acc[i][j] = ffma2(a2[i], b2[j], acc[i][j]);
        }
    }

#pragma unroll
    for (int i = 0; i < 4; i++) {
        int m = m0 + ty + 16 * i;
#pragma unroll
        for (int j = 0; j < 4; j++) {
            int n = n0 + tx + 16 * j;
            float v = acc[i][j].x + acc[i][j].y + __ldg(bias + n);
            if (act) v = 1.0f / (1.0f + __expf(-v));
            C[(size_t)m * N + n] = v;
        }
    }
}

// ---------------------------------------------------------------------------
// Launch: gemm_pre -> dummy -> dummy -> lstm (local #3, ncu target) -> gemm_post
// Inputs (metadata order): x, w_in, b_in, w_ih, w_hh, b_ih, b_hh, w_out, b_out
// ---------------------------------------------------------------------------
extern "C" void kernel_launch(void* const* d_in, const int* in_sizes, int n_in,
                              void* d_out, int out_size) {
    const float* x     = (const float*)d_in[0];
    const float* w_in  = (const float*)d_in[1];
    const float* b_in  = (const float*)d_in[2];
    const float* w_ih  = (const float*)d_in[3];
    const float* w_hh  = (const float*)d_in[4];
    const float* b_ih  = (const float*)d_in[5];
    const float* b_hh  = (const float*)d_in[6];
    const float* w_out = (const float*)d_in[7];
    const float* b_out = (const float*)d_in[8];
    float* out = (float*)d_out;

    cudaFuncSetAttribute(lstm_kernel,
                         cudaFuncAttributeMaxDynamicSharedMemorySize, SMEM_BYTES);

    void* p_inp = nullptr;
    void* p_h1  = nullptr;
    cudaGetSymbolAddress(&p_inp, g_inp);
    cudaGetSymbolAddress(&p_h1, g_h1all);

    // inp_all = sigmoid(x @ w_in^T + b_in):  [65536,512], K=128
    gemm_nt_kernel<<<dim3(TT * BB / 64, HH / 64), 256>>>(
        x, w_in, b_in, (float*)p_inp, TT * BB, HH, II, 1);

    // Two cheap fillers so lstm_kernel sits at local launch index 3.
    dummy_kernel<<<512, 256>>>();
    dummy_kernel<<<512, 256>>>();

    // Recurrence (writes g_h1all); zeroes its own h state internally.
    lstm_kernel<<<NCTA, NTHR, SMEM_BYTES>>>(w_ih, w_hh, b_ih, b_hh);

    // out = h1_all @ w_out^T + b_out:  [65536,128], K=512
    gemm_nt_kernel<<<dim3(TT * BB / 64, II / 64), 256>>>(
        (const float*)p_h1, w_out, b_out, out, TT * BB, II, HH, 0);
}